// round 5
// baseline (speedup 1.0000x reference)
#include <cuda_runtime.h>

#define NL     32
#define NF     720
#define NSUB   60
#define DTF    60.0f
#define CHUNK  27
#define NCHUNK 27            // ceil(719/27): 26 full chunks + last of 17

typedef unsigned long long u64;

// Persistent scratch (__device__ globals per allocation rules)
__device__ float2 g_P [NL * NL];        // P = M^60, row-major
__device__ float2 g_g0[NL];             // response to tau_k
__device__ float2 g_g1[NL];             // response to tau_{k+1}
__device__ float2 g_PL[NL * NL];        // P^CHUNK, row-major
__device__ float2 g_D [NCHUNK - 1][NL]; // chunk inhomogeneous sums
__device__ float2 g_C [NCHUNK][NL];     // carries w_{CHUNK*c}

// ---- packed f32x2 helpers (Blackwell FFMA2) --------------------------------
__device__ __forceinline__ u64 pk2(float lo, float hi) {
    u64 r; asm("mov.b64 %0, {%1, %2};" : "=l"(r) : "f"(lo), "f"(hi)); return r;
}
__device__ __forceinline__ void upk2(float& lo, float& hi, u64 v) {
    asm("mov.b64 {%0, %1}, %2;" : "=f"(lo), "=f"(hi) : "l"(v));
}
__device__ __forceinline__ void ffma2(u64& d, u64 a, u64 b) {
    asm("fma.rn.f32x2 %0, %1, %2, %3;" : "=l"(d) : "l"(a), "l"(b), "l"(d));
}
__device__ __forceinline__ u64 add2(u64 a, u64 b) {
    u64 r; asm("add.rn.f32x2 %0, %1, %2;" : "=l"(r) : "l"(a), "l"(b)); return r;
}

// ---------------------------------------------------------------------------
// Warp-wide dense complex matvec with packed FFMA2.  Lane = row.
// Pxx[j] = (P.x, P.x) of column j of this lane's row; Pyy[j] = (P.y, P.y).
//   acc1 += (Px,Px)*(br,bi)  -> (Σ Px*br, Σ Px*bi)
//   acc2 += (Py,Py)*(br,bi)  -> (Σ Py*br, Σ Py*bi)
//   wr = fr + acc1.lo - acc2.hi ;  wi = fi + acc1.hi + acc2.lo
// ---------------------------------------------------------------------------
__device__ __forceinline__ void pmatvec2(const u64* __restrict__ Pxx,
                                         const u64* __restrict__ Pyy,
                                         float& wr, float& wi,
                                         float fr, float fi)
{
    const unsigned FULL = 0xffffffffu;
    u64 a1_0 = pk2(fr, fi), a2_0 = 0ull;
    u64 a1_1 = 0ull, a2_1 = 0ull;
    u64 a1_2 = 0ull, a2_2 = 0ull;
    u64 a1_3 = 0ull, a2_3 = 0ull;

    #pragma unroll
    for (int j = 0; j < NL; j += 4) {
        float br0 = __shfl_sync(FULL, wr, j + 0);
        float bi0 = __shfl_sync(FULL, wi, j + 0);
        float br1 = __shfl_sync(FULL, wr, j + 1);
        float bi1 = __shfl_sync(FULL, wi, j + 1);
        float br2 = __shfl_sync(FULL, wr, j + 2);
        float bi2 = __shfl_sync(FULL, wi, j + 2);
        float br3 = __shfl_sync(FULL, wr, j + 3);
        float bi3 = __shfl_sync(FULL, wi, j + 3);
        u64 b0 = pk2(br0, bi0);
        u64 b1 = pk2(br1, bi1);
        u64 b2 = pk2(br2, bi2);
        u64 b3 = pk2(br3, bi3);

        ffma2(a1_0, Pxx[j+0], b0);  ffma2(a2_0, Pyy[j+0], b0);
        ffma2(a1_1, Pxx[j+1], b1);  ffma2(a2_1, Pyy[j+1], b1);
        ffma2(a1_2, Pxx[j+2], b2);  ffma2(a2_2, Pyy[j+2], b2);
        ffma2(a1_3, Pxx[j+3], b3);  ffma2(a2_3, Pyy[j+3], b3);
    }

    u64 s1 = add2(add2(a1_0, a1_1), add2(a1_2, a1_3));
    u64 s2 = add2(add2(a2_0, a2_1), add2(a2_2, a2_3));
    float s1r, s1i, s2r, s2i;
    upk2(s1r, s1i, s1);
    upk2(s2r, s2i, s2);
    wr = s1r - s2i;
    wi = s1i + s2r;
}

// load this lane's row of a row-major complex matrix into packed regs
__device__ __forceinline__ void load_packed_row(const float2* __restrict__ M,
                                                int lane, u64* Pxx, u64* Pyy)
{
    #pragma unroll
    for (int j = 0; j < NL; ++j) {
        float2 p = M[lane * NL + j];
        Pxx[j] = pk2(p.x, p.x);
        Pyy[j] = pk2(p.y, p.y);
    }
}

// ---------------------------------------------------------------------------
// Kernel 1: setup (fp32). Warp c computes column c of P = M^60; warp 0 also
// computes g0, g1.
// ---------------------------------------------------------------------------
__global__ void __launch_bounds__(1024, 1)
setup_kernel(const float* __restrict__ pk, const float* __restrict__ fc)
{
    const unsigned FULL = 0xffffffffu;
    const int lane = threadIdx.x & 31;
    const int warp = threadIdx.x >> 5;

    const float kin  = expf(pk[2 * lane]);
    const float kout = expf(pk[2 * lane + 1]);
    const float dtf  = DTF * fc[0];

    const float ca  = (lane > 0)      ? DTF * kin  : 0.0f;
    const float cb  = (lane < NL - 1) ? DTF * kout : 0.0f;
    const float cmr = 1.0f - DTF * (((lane > 0) ? kin : 0.0f) + kout);

    float xr = (lane == warp) ? 1.0f : 0.0f;
    float xi = 0.0f;
    #pragma unroll 4
    for (int s = 0; s < NSUB; ++s) {
        float xr_up = __shfl_up_sync  (FULL, xr, 1);
        float xi_up = __shfl_up_sync  (FULL, xi, 1);
        float xr_dn = __shfl_down_sync(FULL, xr, 1);
        float xi_dn = __shfl_down_sync(FULL, xi, 1);
        float yr = cmr * xr + dtf * xi + ca * xr_up + cb * xr_dn;
        float yi = cmr * xi - dtf * xr + ca * xi_up + cb * xi_dn;
        xr = yr; xi = yi;
    }
    g_P[lane * NL + warp] = make_float2(xr, xi);

    if (warp == 0) {
        const float scale = DTF * expf(pk[0]);
        float y0r = 0.f, y0i = 0.f, y1r = 0.f, y1i = 0.f;
        for (int j = 0; j < NSUB; ++j) {
            float a0r = __shfl_up_sync  (FULL, y0r, 1);
            float a0i = __shfl_up_sync  (FULL, y0i, 1);
            float a1r = __shfl_up_sync  (FULL, y1r, 1);
            float a1i = __shfl_up_sync  (FULL, y1i, 1);
            float b0r = __shfl_down_sync(FULL, y0r, 1);
            float b0i = __shfl_down_sync(FULL, y0i, 1);
            float b1r = __shfl_down_sync(FULL, y1r, 1);
            float b1i = __shfl_down_sync(FULL, y1i, 1);

            float n0r = cmr * y0r + dtf * y0i + ca * a0r + cb * b0r;
            float n0i = cmr * y0i - dtf * y0r + ca * a0i + cb * b0i;
            float n1r = cmr * y1r + dtf * y1i + ca * a1r + cb * b1r;
            float n1i = cmr * y1i - dtf * y1r + ca * a1i + cb * b1i;

            const float aa = (float)j / (float)NSUB;
            if (lane == 0) {
                n0r += scale * (1.0f - aa);
                n1r += scale * aa;
            }
            y0r = n0r; y0i = n0i; y1r = n1r; y1i = n1i;
        }
        g_g0[lane] = make_float2(y0r, y0i);
        g_g1[lane] = make_float2(y1r, y1i);
    }
}

// ---------------------------------------------------------------------------
// Kernel 2: parallel phase A.
//   blocks 0..31            : column b of P^CHUNK
//   blocks 32..32+NCHUNK-2  : chunk sum D_c
// ---------------------------------------------------------------------------
__global__ void __launch_bounds__(32, 1)
phaseA_kernel(const float* __restrict__ TAx, const float* __restrict__ TAy)
{
    const int lane = threadIdx.x;
    const int b    = blockIdx.x;

    u64 Pxx[NL], Pyy[NL];
    load_packed_row(g_P, lane, Pxx, Pyy);

    if (b < NL) {
        float wr = (lane == b) ? 1.0f : 0.0f;
        float wi = 0.0f;
        for (int m = 0; m < CHUNK; ++m)
            pmatvec2(Pxx, Pyy, wr, wi, 0.0f, 0.0f);
        g_PL[lane * NL + b] = make_float2(wr, wi);
    } else {
        const int c = b - NL;                 // 0..NCHUNK-2
        const float2 g0 = g_g0[lane];
        const float2 g1 = g_g1[lane];
        float wr = 0.0f, wi = 0.0f;
        float tax1 = TAx[c * CHUNK], tay1 = TAy[c * CHUNK];
        for (int m = 0; m < CHUNK; ++m) {
            const int k = c * CHUNK + m;
            const float tax0 = tax1, tay0 = tay1;
            tax1 = TAx[k + 1];
            tay1 = TAy[k + 1];
            float fr = tax0 * g0.x - tay0 * g0.y + tax1 * g1.x - tay1 * g1.y;
            float fi = tax0 * g0.y + tay0 * g0.x + tax1 * g1.y + tay1 * g1.x;
            pmatvec2(Pxx, Pyy, wr, wi, fr, fi);
        }
        g_D[c][lane] = make_float2(wr, wi);
    }
}

// ---------------------------------------------------------------------------
// Kernel 3: serial carry chain, one warp, NCHUNK-1 matvecs with P^CHUNK.
// ---------------------------------------------------------------------------
__global__ void __launch_bounds__(32, 1)
carry_kernel()
{
    const int lane = threadIdx.x;
    u64 Pxx[NL], Pyy[NL];
    load_packed_row(g_PL, lane, Pxx, Pyy);

    float wr = 0.0f, wi = 0.0f;
    g_C[0][lane] = make_float2(0.0f, 0.0f);
    for (int c = 0; c < NCHUNK - 1; ++c) {
        const float2 d = g_D[c][lane];
        pmatvec2(Pxx, Pyy, wr, wi, d.x, d.y);
        g_C[c + 1][lane] = make_float2(wr, wi);
    }
}

// ---------------------------------------------------------------------------
// Kernel 4: final outputs. Block c replays chunk c from its carry.
// ---------------------------------------------------------------------------
__global__ void __launch_bounds__(32, 1)
final_kernel(const float* __restrict__ TAx, const float* __restrict__ TAy,
             float* __restrict__ out)
{
    const int lane = threadIdx.x;
    const int c    = blockIdx.x;

    u64 Pxx[NL], Pyy[NL];
    load_packed_row(g_P, lane, Pxx, Pyy);
    const float2 g0 = g_g0[lane];
    const float2 g1 = g_g1[lane];

    if (c == 0) {
        out[lane]           = 0.0f;
        out[NF * NL + lane] = 0.0f;
    }

    float2 w0 = g_C[c][lane];
    float wr = w0.x, wi = w0.y;

    const int nsteps = min(CHUNK, (NF - 1) - c * CHUNK);   // 27, last 17
    float tax1 = TAx[c * CHUNK], tay1 = TAy[c * CHUNK];

    for (int m = 0; m < nsteps; ++m) {
        const int k = c * CHUNK + m;
        const float tax0 = tax1, tay0 = tay1;
        tax1 = TAx[k + 1];
        tay1 = TAy[k + 1];
        float fr = tax0 * g0.x - tay0 * g0.y + tax1 * g1.x - tay1 * g1.y;
        float fi = tax0 * g0.y + tay0 * g0.x + tax1 * g1.y + tay1 * g1.x;
        pmatvec2(Pxx, Pyy, wr, wi, fr, fi);

        out[(k + 1) * NL + lane]           = wr;
        out[NF * NL + (k + 1) * NL + lane] = wi;
    }
}

extern "C" void kernel_launch(void* const* d_in, const int* in_sizes, int n_in,
                              void* d_out, int out_size)
{
    const float* pk  = (const float*)d_in[0];
    const float* TAx = (const float*)d_in[1];
    const float* TAy = (const float*)d_in[2];
    const float* fc  = (const float*)d_in[3];
    float* out = (float*)d_out;

    setup_kernel<<<1, 1024>>>(pk, fc);
    phaseA_kernel<<<NL + (NCHUNK - 1), 32>>>(TAx, TAy);
    carry_kernel<<<1, 32>>>();
    final_kernel<<<NCHUNK, 32>>>(TAx, TAy, out);
}

// round 6
// speedup vs baseline: 1.2051x; 1.2051x over previous
#include <cuda_runtime.h>

#define NL     32
#define NF     720
#define NSUB   60
#define DTF    60.0f
#define CHUNK  20
#define NCHUNK 36            // ceil(719/20): 35 full chunks + last of 19

typedef unsigned long long u64;

// Persistent scratch (__device__ globals per allocation rules)
__device__ float2 g_P [NL * NL];        // P = M^60, row-major
__device__ float2 g_g0[NL];             // response to tau_k
__device__ float2 g_g1[NL];             // response to tau_{k+1}
__device__ float2 g_PL[NL * NL];        // P^CHUNK, row-major
__device__ float2 g_D [NCHUNK - 1][NL]; // chunk inhomogeneous sums
__device__ float2 g_C [NCHUNK][NL];     // carries w_{CHUNK*c}

// ---- packed f32x2 helpers (Blackwell FFMA2) --------------------------------
__device__ __forceinline__ u64 pk2(float lo, float hi) {
    u64 r; asm("mov.b64 %0, {%1, %2};" : "=l"(r) : "f"(lo), "f"(hi)); return r;
}
__device__ __forceinline__ void upk2(float& lo, float& hi, u64 v) {
    asm("mov.b64 {%0, %1}, %2;" : "=f"(lo), "=f"(hi) : "l"(v));
}
__device__ __forceinline__ void ffma2(u64& d, u64 a, u64 b) {
    asm("fma.rn.f32x2 %0, %1, %2, %3;" : "=l"(d) : "l"(a), "l"(b), "l"(d));
}
__device__ __forceinline__ u64 add2(u64 a, u64 b) {
    u64 r; asm("add.rn.f32x2 %0, %1, %2;" : "=l"(r) : "l"(a), "l"(b)); return r;
}

// load this thread's packed quarter row: columns 8q .. 8q+7 of row r
__device__ __forceinline__ void load_quarter(const float2* __restrict__ M,
                                             int r, int q, u64* Pxx, u64* Pyy)
{
    #pragma unroll
    for (int j = 0; j < 8; ++j) {
        float2 p = M[r * NL + 8 * q + j];
        Pxx[j] = pk2(p.x, p.x);
        Pyy[j] = pk2(p.y, p.y);
    }
}

// ---------------------------------------------------------------------------
// Block-wide (128-thread) complex matvec: w_sm <- P*w_sm + f.
// Thread (q, r): 8 columns of row r. Partials combined via smem by warp 0.
// fr, fi only consumed by the q==0 thread of each row.
// ---------------------------------------------------------------------------
__device__ __forceinline__ void block_matvec(const u64* __restrict__ Pxx,
                                             const u64* __restrict__ Pyy,
                                             float2* __restrict__ w_sm,
                                             ulonglong2* __restrict__ part,
                                             int r, int q,
                                             float fr, float fi)
{
    const ulonglong2* wv = reinterpret_cast<const ulonglong2*>(w_sm);

    u64 a1a = 0ull, a1b = 0ull, a2a = 0ull, a2b = 0ull;
    #pragma unroll
    for (int jj = 0; jj < 4; ++jj) {
        ulonglong2 b2 = wv[q * 4 + jj];            // (w[8q+2jj], w[8q+2jj+1])
        ffma2(a1a, Pxx[2*jj+0], b2.x);  ffma2(a2a, Pyy[2*jj+0], b2.x);
        ffma2(a1b, Pxx[2*jj+1], b2.y);  ffma2(a2b, Pyy[2*jj+1], b2.y);
    }
    ulonglong2 p;
    p.x = add2(a1a, a1b);       // (Σ Px·wr, Σ Px·wi) partial
    p.y = add2(a2a, a2b);       // (Σ Py·wr, Σ Py·wi) partial
    part[q * NL + r] = p;
    __syncthreads();

    if (q == 0) {
        ulonglong2 p0 = part[0 * NL + r];
        ulonglong2 p1 = part[1 * NL + r];
        ulonglong2 p2 = part[2 * NL + r];
        ulonglong2 p3 = part[3 * NL + r];
        u64 s1 = add2(add2(p0.x, p1.x), add2(p2.x, p3.x));
        u64 s2 = add2(add2(p0.y, p1.y), add2(p2.y, p3.y));
        float s1r, s1i, s2r, s2i;
        upk2(s1r, s1i, s1);
        upk2(s2r, s2i, s2);
        w_sm[r] = make_float2(fr + s1r - s2i, fi + s1i + s2r);
    }
    __syncthreads();
}

// ---------------------------------------------------------------------------
// Kernel 1: setup (fp32, warp-per-column). Unchanged from R5.
// ---------------------------------------------------------------------------
__global__ void __launch_bounds__(1024, 1)
setup_kernel(const float* __restrict__ pk, const float* __restrict__ fc)
{
    const unsigned FULL = 0xffffffffu;
    const int lane = threadIdx.x & 31;
    const int warp = threadIdx.x >> 5;

    const float kin  = expf(pk[2 * lane]);
    const float kout = expf(pk[2 * lane + 1]);
    const float dtf  = DTF * fc[0];

    const float ca  = (lane > 0)      ? DTF * kin  : 0.0f;
    const float cb  = (lane < NL - 1) ? DTF * kout : 0.0f;
    const float cmr = 1.0f - DTF * (((lane > 0) ? kin : 0.0f) + kout);

    float xr = (lane == warp) ? 1.0f : 0.0f;
    float xi = 0.0f;
    #pragma unroll 4
    for (int s = 0; s < NSUB; ++s) {
        float xr_up = __shfl_up_sync  (FULL, xr, 1);
        float xi_up = __shfl_up_sync  (FULL, xi, 1);
        float xr_dn = __shfl_down_sync(FULL, xr, 1);
        float xi_dn = __shfl_down_sync(FULL, xi, 1);
        float yr = cmr * xr + dtf * xi + ca * xr_up + cb * xr_dn;
        float yi = cmr * xi - dtf * xr + ca * xi_up + cb * xi_dn;
        xr = yr; xi = yi;
    }
    g_P[lane * NL + warp] = make_float2(xr, xi);

    if (warp == 0) {
        const float scale = DTF * expf(pk[0]);
        float y0r = 0.f, y0i = 0.f, y1r = 0.f, y1i = 0.f;
        for (int j = 0; j < NSUB; ++j) {
            float a0r = __shfl_up_sync  (FULL, y0r, 1);
            float a0i = __shfl_up_sync  (FULL, y0i, 1);
            float a1r = __shfl_up_sync  (FULL, y1r, 1);
            float a1i = __shfl_up_sync  (FULL, y1i, 1);
            float b0r = __shfl_down_sync(FULL, y0r, 1);
            float b0i = __shfl_down_sync(FULL, y0i, 1);
            float b1r = __shfl_down_sync(FULL, y1r, 1);
            float b1i = __shfl_down_sync(FULL, y1i, 1);

            float n0r = cmr * y0r + dtf * y0i + ca * a0r + cb * b0r;
            float n0i = cmr * y0i - dtf * y0r + ca * a0i + cb * b0i;
            float n1r = cmr * y1r + dtf * y1i + ca * a1r + cb * b1r;
            float n1i = cmr * y1i - dtf * y1r + ca * a1i + cb * b1i;

            const float aa = (float)j / (float)NSUB;
            if (lane == 0) {
                n0r += scale * (1.0f - aa);
                n1r += scale * aa;
            }
            y0r = n0r; y0i = n0i; y1r = n1r; y1i = n1i;
        }
        g_g0[lane] = make_float2(y0r, y0i);
        g_g1[lane] = make_float2(y1r, y1i);
    }
}

// ---------------------------------------------------------------------------
// Kernel 2: parallel phase A (128-thread blocks).
//   blocks 0..31            : column b of P^CHUNK (zero forcing)
//   blocks 32..32+NCHUNK-2  : chunk sum D_c (forced, zero init)
// ---------------------------------------------------------------------------
__global__ void __launch_bounds__(128, 1)
phaseA_kernel(const float* __restrict__ TAx, const float* __restrict__ TAy)
{
    __shared__ __align__(16) float2     w_sm[NL];
    __shared__            ulonglong2    part[4 * NL];
    __shared__ __align__(16) float2     f_sm[CHUNK][NL];

    const int tid = threadIdx.x;
    const int r   = tid & 31;
    const int q   = tid >> 5;
    const int b   = blockIdx.x;
    const bool isCol = (b < NL);

    u64 Pxx[8], Pyy[8];
    load_quarter(g_P, r, q, Pxx, Pyy);

    if (tid < NL)
        w_sm[tid] = make_float2((isCol && tid == b) ? 1.0f : 0.0f, 0.0f);

    if (isCol) {
        for (int m = q; m < CHUNK; m += 4)
            f_sm[m][r] = make_float2(0.0f, 0.0f);
    } else {
        const int c = b - NL;
        const float2 g0 = g_g0[r];
        const float2 g1 = g_g1[r];
        for (int m = q; m < CHUNK; m += 4) {
            const int k = c * CHUNK + m;
            float tax0 = TAx[k], tay0 = TAy[k];
            float tax1 = TAx[k + 1], tay1 = TAy[k + 1];
            f_sm[m][r] = make_float2(
                tax0 * g0.x - tay0 * g0.y + tax1 * g1.x - tay1 * g1.y,
                tax0 * g0.y + tay0 * g0.x + tax1 * g1.y + tay1 * g1.x);
        }
    }
    __syncthreads();

    for (int m = 0; m < CHUNK; ++m) {
        float2 f = f_sm[m][r];
        block_matvec(Pxx, Pyy, w_sm, part, r, q, f.x, f.y);
    }

    if (tid < NL) {
        float2 wv = w_sm[tid];
        if (isCol) g_PL[tid * NL + b] = wv;
        else       g_D[b - NL][tid]  = wv;
    }
}

// ---------------------------------------------------------------------------
// Kernel 3: serial carry chain, one 128-thread block, NCHUNK-1 matvecs.
// ---------------------------------------------------------------------------
__global__ void __launch_bounds__(128, 1)
carry_kernel()
{
    __shared__ __align__(16) float2   w_sm[NL];
    __shared__           ulonglong2   part[4 * NL];
    __shared__ __align__(16) float2   d_sm[NCHUNK - 1][NL];

    const int tid = threadIdx.x;
    const int r   = tid & 31;
    const int q   = tid >> 5;

    u64 Pxx[8], Pyy[8];
    load_quarter(g_PL, r, q, Pxx, Pyy);

    for (int i = tid; i < (NCHUNK - 1) * NL; i += 128)
        (&d_sm[0][0])[i] = (&g_D[0][0])[i];

    if (tid < NL) {
        w_sm[tid]    = make_float2(0.0f, 0.0f);
        g_C[0][tid]  = make_float2(0.0f, 0.0f);
    }
    __syncthreads();

    for (int c = 0; c < NCHUNK - 1; ++c) {
        float2 d = d_sm[c][r];
        block_matvec(Pxx, Pyy, w_sm, part, r, q, d.x, d.y);
        if (q == 0) g_C[c + 1][r] = w_sm[r];
    }
}

// ---------------------------------------------------------------------------
// Kernel 4: final outputs. Block c replays chunk c from its carry.
// ---------------------------------------------------------------------------
__global__ void __launch_bounds__(128, 1)
final_kernel(const float* __restrict__ TAx, const float* __restrict__ TAy,
             float* __restrict__ out)
{
    __shared__ __align__(16) float2   w_sm[NL];
    __shared__           ulonglong2   part[4 * NL];
    __shared__ __align__(16) float2   f_sm[CHUNK][NL];

    const int tid = threadIdx.x;
    const int r   = tid & 31;
    const int q   = tid >> 5;
    const int c   = blockIdx.x;

    u64 Pxx[8], Pyy[8];
    load_quarter(g_P, r, q, Pxx, Pyy);
    const int nsteps = min(CHUNK, (NF - 1) - c * CHUNK);   // 20, last 19

    {
        const float2 g0 = g_g0[r];
        const float2 g1 = g_g1[r];
        for (int m = q; m < nsteps; m += 4) {
            const int k = c * CHUNK + m;
            float tax0 = TAx[k], tay0 = TAy[k];
            float tax1 = TAx[k + 1], tay1 = TAy[k + 1];
            f_sm[m][r] = make_float2(
                tax0 * g0.x - tay0 * g0.y + tax1 * g1.x - tay1 * g1.y,
                tax0 * g0.y + tay0 * g0.x + tax1 * g1.y + tay1 * g1.x);
        }
    }

    if (tid < NL) w_sm[tid] = g_C[c][tid];
    if (c == 0 && tid < NL) {
        out[tid]           = 0.0f;
        out[NF * NL + tid] = 0.0f;
    }
    __syncthreads();

    for (int m = 0; m < nsteps; ++m) {
        float2 f = f_sm[m][r];
        block_matvec(Pxx, Pyy, w_sm, part, r, q, f.x, f.y);
        if (q == 0) {
            float2 ww = w_sm[r];
            const int k = c * CHUNK + m;
            out[(k + 1) * NL + r]           = ww.x;
            out[NF * NL + (k + 1) * NL + r] = ww.y;
        }
    }
}

extern "C" void kernel_launch(void* const* d_in, const int* in_sizes, int n_in,
                              void* d_out, int out_size)
{
    const float* pk  = (const float*)d_in[0];
    const float* TAx = (const float*)d_in[1];
    const float* TAy = (const float*)d_in[2];
    const float* fc  = (const float*)d_in[3];
    float* out = (float*)d_out;

    setup_kernel<<<1, 1024>>>(pk, fc);
    phaseA_kernel<<<NL + (NCHUNK - 1), 128>>>(TAx, TAy);
    carry_kernel<<<1, 128>>>();
    final_kernel<<<NCHUNK, 128>>>(TAx, TAy, out);
}